// round 13
// baseline (speedup 1.0000x reference)
#include <cuda_runtime.h>
#include <math_constants.h>
#include <cstdint>

#define BATCH 8
#define NTOK  1024
#define DIM   384
#define NH    12
#define HD    32
#define QSCALE 0.17677669529663687f   // 32^-0.5

// ---------------- scratch (no allocs allowed) ----------------
// g_q, g_kc, g_vc, g_mid, g_xt, g_wqkv, g_wproj hold tf32 bit patterns
// g_vc layout: TRANSPOSED [bh][d][key'] with inner-8 key permutation
__device__ float g_q [BATCH*NH*NTOK*HD];
__device__ float g_k [BATCH*NH*NTOK*HD];
__device__ float g_v [BATCH*NH*NTOK*HD];
__device__ float g_kc[BATCH*NH*NTOK*HD];
__device__ float g_vc[BATCH*NH*NTOK*HD];
__device__ float g_mid[BATCH*NTOK*DIM];
__device__ uint32_t g_xt   [BATCH*NTOK*DIM];
__device__ uint32_t g_wqkv [DIM*3*DIM];
__device__ uint32_t g_wproj[DIM*DIM];

// ---------------- helpers ----------------
__device__ __forceinline__ uint32_t f2tf(float f) {
    uint32_t r;
    asm("cvt.rna.tf32.f32 %0, %1;" : "=r"(r) : "f"(f));
    return r;
}

__device__ __forceinline__ void mma_tf32(float c[4], const uint32_t a[4], const uint32_t b[2]) {
    asm volatile(
        "mma.sync.aligned.m16n8k8.row.col.f32.tf32.tf32.f32 "
        "{%0,%1,%2,%3},{%4,%5,%6,%7},{%8,%9},{%0,%1,%2,%3};"
        : "+f"(c[0]), "+f"(c[1]), "+f"(c[2]), "+f"(c[3])
        : "r"(a[0]), "r"(a[1]), "r"(a[2]), "r"(a[3]), "r"(b[0]), "r"(b[1]));
}

__device__ __forceinline__ uint32_t s2u(const void* p) {
    return (uint32_t)__cvta_generic_to_shared(p);
}

__device__ __forceinline__ void ldsm4(uint32_t r[4], uint32_t saddr) {
    asm volatile("ldmatrix.sync.aligned.m8n8.x4.shared.b16 {%0,%1,%2,%3}, [%4];"
        : "=r"(r[0]), "=r"(r[1]), "=r"(r[2]), "=r"(r[3]) : "r"(saddr));
}

__device__ __forceinline__ void cp16(uint32_t dst, const void* src) {
    asm volatile("cp.async.ca.shared.global [%0], [%1], 16;" :: "r"(dst), "l"(src));
}
__device__ __forceinline__ void cp_commit() {
    asm volatile("cp.async.commit_group;");
}
__device__ __forceinline__ void cp_wait0() {
    asm volatile("cp.async.wait_group 0;");
}

__device__ __forceinline__ float2 ldg_cg2(const float* p) {
    float2 v;
    asm volatile("ld.global.cg.v2.f32 {%0,%1}, [%2];"
        : "=f"(v.x), "=f"(v.y) : "l"(p));
    return v;
}

// ---------------- one-time tf32 pre-conversion ----------------
__global__ __launch_bounds__(256) void cvt_pack(
    const float* __restrict__ x, const float* __restrict__ wq,
    const float* __restrict__ wp)
{
    const int t = blockIdx.x * 256 + threadIdx.x;
    const float4* src;
    uint32_t* dst;
    int i;
    if (t < 786432)        { src = (const float4*)x;  dst = g_xt;    i = t; }
    else if (t < 897024)   { src = (const float4*)wq; dst = g_wqkv;  i = t - 786432; }
    else if (t < 933888)   { src = (const float4*)wp; dst = g_wproj; i = t - 897024; }
    else return;
    const float4 v = src[i];
    *(uint4*)&dst[i * 4] = make_uint4(f2tf(v.x), f2tf(v.y), f2tf(v.z), f2tf(v.w));
}

// ---------------- wide-tile GEMM: 128x128 block ----------------
// MODE 0: qkv (NDIM=1152), scatter into g_q (scaled tf32) / g_k / g_v.
// MODE 1: proj (NDIM=384), row-major float output.
template<int NDIM, int MODE>
__global__ __launch_bounds__(256, 2) void gemm_wide(
    const uint32_t* __restrict__ A, const uint32_t* __restrict__ B,
    const float* __restrict__ bias, float* __restrict__ Cout)
{
    constexpr int KDIM = 384;
    constexpr int NK   = KDIM / 16;

    __shared__ uint32_t As[2][128][20];   // [m][k]
    __shared__ uint32_t Bs[2][128][20];   // [n][k]

    const int m0  = blockIdx.y * 128;
    const int n0  = blockIdx.x * 128;
    const int tid  = threadIdx.x;
    const int warp = tid >> 5;
    const int lane = tid & 31;
    const int g = lane >> 2;
    const int q = lane & 3;
    const int wm = (warp & 3) * 32;
    const int wn = (warp >> 2) * 64;

    const int ldrow = (lane & 7) | ((lane & 16) >> 1);
    const int ldcol = ((lane >> 3) & 1) * 4;

    const int ar0 = (tid)       >> 2, ak0 = ((tid)       & 3) * 4;
    const int ar1 = (tid + 256) >> 2, ak1 = ((tid + 256) & 3) * 4;
    const int bn   = tid & 127;
    const int bkq0 = (tid >> 7) * 4;

    float acc[2][8][4];
#pragma unroll
    for (int mi = 0; mi < 2; mi++)
#pragma unroll
        for (int ni = 0; ni < 8; ni++)
#pragma unroll
            for (int i = 0; i < 4; i++) acc[mi][ni][i] = 0.f;

    uint32_t pb[2][4];

    cp16(s2u(&As[0][ar0][ak0]), A + (size_t)(m0 + ar0) * KDIM + ak0);
    cp16(s2u(&As[0][ar1][ak1]), A + (size_t)(m0 + ar1) * KDIM + ak1);
    cp_commit();
#pragma unroll
    for (int i = 0; i < 2; i++)
#pragma unroll
        for (int j = 0; j < 4; j++)
            pb[i][j] = B[(size_t)(bkq0 + i * 8 + j) * NDIM + n0 + bn];
#pragma unroll
    for (int i = 0; i < 2; i++)
        *(uint4*)&Bs[0][bn][bkq0 + i * 8] =
            make_uint4(pb[i][0], pb[i][1], pb[i][2], pb[i][3]);
    cp_wait0();
    __syncthreads();

    for (int kb = 0; kb < NK; kb++) {
        const int  cur      = kb & 1;
        const bool has_next = (kb + 1) < NK;
        const int  nxt      = cur ^ 1;

        if (has_next) {
            const int k0 = (kb + 1) * 16;
#pragma unroll
            for (int i = 0; i < 2; i++)
#pragma unroll
                for (int j = 0; j < 4; j++)
                    pb[i][j] = B[(size_t)(k0 + bkq0 + i * 8 + j) * NDIM + n0 + bn];
            cp16(s2u(&As[nxt][ar0][ak0]), A + (size_t)(m0 + ar0) * KDIM + k0 + ak0);
            cp16(s2u(&As[nxt][ar1][ak1]), A + (size_t)(m0 + ar1) * KDIM + k0 + ak1);
            cp_commit();
        }

#pragma unroll
        for (int s = 0; s < 2; s++) {
            uint32_t af[2][4], bf4[4][4];
#pragma unroll
            for (int mi = 0; mi < 2; mi++) {
                uint32_t r[4];
                ldsm4(r, s2u(&As[cur][wm + mi * 16 + ldrow][s * 8 + ldcol]));
                af[mi][0] = r[0]; af[mi][1] = r[2];
                af[mi][2] = r[1]; af[mi][3] = r[3];
            }
#pragma unroll
            for (int nj = 0; nj < 4; nj++)
                ldsm4(bf4[nj], s2u(&Bs[cur][wn + nj * 16 + ldrow][s * 8 + ldcol]));
#pragma unroll
            for (int mi = 0; mi < 2; mi++)
#pragma unroll
                for (int ni = 0; ni < 8; ni++)
                    mma_tf32(acc[mi][ni], af[mi], &bf4[ni >> 1][(ni & 1) * 2]);
        }

        if (has_next) {
#pragma unroll
            for (int i = 0; i < 2; i++)
                *(uint4*)&Bs[nxt][bn][bkq0 + i * 8] =
                    make_uint4(pb[i][0], pb[i][1], pb[i][2], pb[i][3]);
            cp_wait0();
        }
        __syncthreads();
    }

#pragma unroll
    for (int mi = 0; mi < 2; mi++) {
#pragma unroll
        for (int rr = 0; rr < 2; rr++) {
            const int row  = m0 + wm + mi * 16 + g + rr * 8;
            const int bidx = row >> 10;
            const int n    = row & 1023;
#pragma unroll
            for (int ni = 0; ni < 8; ni++) {
                const int col = n0 + wn + ni * 8 + 2 * q;
                const float v0 = acc[mi][ni][rr * 2]     + bias[col];
                const float v1 = acc[mi][ni][rr * 2 + 1] + bias[col + 1];
                if (MODE == 0) {
                    const int s = col / DIM;
                    const int r = col - s * DIM;
                    const int h = r >> 5;
                    const int d = r & 31;
                    const int off = (((bidx * NH + h) * NTOK + n) << 5) + d;
                    if (s == 0) {
                        *(float2*)&g_q[off] = make_float2(
                            __uint_as_float(f2tf(v0 * QSCALE)),
                            __uint_as_float(f2tf(v1 * QSCALE)));
                    } else {
                        float* dst = (s == 1) ? g_k : g_v;
                        *(float2*)&dst[off] = make_float2(v0, v1);
                    }
                } else {
                    *(float2*)&Cout[(size_t)row * NDIM + col] = make_float2(v0, v1);
                }
            }
        }
    }
}

// ---------------- depthwise 3x3 SAME conv on K and V ----------------
// K written [bh][key][d] (tf32), coalesced. V written TRANSPOSED
// [bh][d][key'] (tf32, inner-8 perm) via an smem 32x32 transpose so the
// global stores are coalesced 128B lines (was 4x scattered 4B stores).
__global__ __launch_bounds__(256) void dwconv_kernel(
    const float* __restrict__ w, const float* __restrict__ cb)
{
    __shared__ float sv[32][33];

    const int t   = blockIdx.x * 256 + threadIdx.x;
    const int d4  = (t & 7) * 4;
    const int n   = (t >> 3) & 1023;
    const int img = t >> 13;
    const int y = n >> 5, x = n & 31;
    const int base = img << 15;

    float4 wr[9];
#pragma unroll
    for (int j = 0; j < 9; j++)
        wr[j] = make_float4(w[(d4 + 0) * 9 + j], w[(d4 + 1) * 9 + j],
                            w[(d4 + 2) * 9 + j], w[(d4 + 3) * 9 + j]);

    float4 aK = *(const float4*)&cb[d4];
    float4 aV = aK;
#pragma unroll
    for (int ky = 0; ky < 3; ky++) {
        const int yy = y + ky - 1;
        if (yy < 0 || yy > 31) continue;
#pragma unroll
        for (int kx = 0; kx < 3; kx++) {
            const int xx = x + kx - 1;
            if (xx < 0 || xx > 31) continue;
            const float4 wv = wr[ky * 3 + kx];
            const int off = base + (((yy << 5) | xx) << 5) + d4;
            const float4 kv = *(const float4*)&g_k[off];
            const float4 vv = *(const float4*)&g_v[off];
            aK.x += kv.x * wv.x; aK.y += kv.y * wv.y;
            aK.z += kv.z * wv.z; aK.w += kv.w * wv.w;
            aV.x += vv.x * wv.x; aV.y += vv.y * wv.y;
            aV.z += vv.z * wv.z; aV.w += vv.w * wv.w;
        }
    }
    const int out = base + (n << 5) + d4;
    *(float4*)&g_kc[out] = make_float4(
        __uint_as_float(f2tf(aK.x)), __uint_as_float(f2tf(aK.y)),
        __uint_as_float(f2tf(aK.z)), __uint_as_float(f2tf(aK.w)));

    // stage V (tf32 bits) into smem transposed: sv[d][n_local]
    const int nl = n & 31;
    sv[d4 + 0][nl] = __uint_as_float(f2tf(aV.x));
    sv[d4 + 1][nl] = __uint_as_float(f2tf(aV.y));
    sv[d4 + 2][nl] = __uint_as_float(f2tf(aV.z));
    sv[d4 + 3][nl] = __uint_as_float(f2tf(aV.w));
    __syncthreads();

    // coalesced V write: each warp writes 4 d-rows of 32 permuted keys
    const int lane  = t & 31;
    const int wid   = (threadIdx.x >> 5) & 7;
    const int nbase = n & ~31;           // block's 32-key range start
    const int j     = lane & 7;
    const int nper  = (lane & ~7) | ((j & 1) ? (4 + (j >> 1)) : (j >> 1));
#pragma unroll
    for (int r = 0; r < 4; r++) {
        const int dd = wid * 4 + r;
        g_vc[base + (dd << 10) + nbase + nper] = sv[dd][lane];
    }
}

// ---------------- flash attention: M=32 per warp, shared K/V fragments ----
// grid (96, 8): (b*NH h-major, 128-query tile). 128 threads = 4 warps x 32
// rows. Fixed-max softmax; l via ones-column MMA. Bias loads use ld.global.cg
// (L2-only; no intra-block reuse) to keep l1tex free for ldmatrix.
__global__ __launch_bounds__(128, 3) void attn_mma_kernel(const float* __restrict__ bias)
{
    __shared__ uint32_t Ks[2][64][36];   // [key][d]
    __shared__ uint32_t Vt[2][32][68];   // [d][key'] -- GEMM-B layout

    const int bhx = blockIdx.x;
    const int qt  = blockIdx.y;
    const int h   = bhx >> 3;
    const int b   = bhx & 7;
    const int bh  = b * NH + h;
    const int tid  = threadIdx.x;
    const int warp = tid >> 5;
    const int lane = tid & 31;
    const int g = lane >> 2;
    const int q = lane & 3;

    const int ldrow = (lane & 7) | ((lane & 16) >> 1);
    const int ldcol = ((lane >> 3) & 1) * 4;

    const int rbase = qt * 128 + warp * 32;

    uint32_t qa[2][4][4];
#pragma unroll
    for (int mi = 0; mi < 2; mi++) {
        const float* q0 = g_q + ((bh * NTOK + rbase + mi * 16 + g) << 5);
        const float* q1 = q0 + (8 << 5);
#pragma unroll
        for (int kk = 0; kk < 4; kk++) {
            qa[mi][kk][0] = __float_as_uint(q0[kk * 8 + q]);
            qa[mi][kk][1] = __float_as_uint(q1[kk * 8 + q]);
            qa[mi][kk][2] = __float_as_uint(q0[kk * 8 + q + 4]);
            qa[mi][kk][3] = __float_as_uint(q1[kk * 8 + q + 4]);
        }
    }

    const float* br[4];
#pragma unroll
    for (int i = 0; i < 4; i++)
        br[i] = bias + ((size_t)h * NTOK + rbase + i * 8 + g) * NTOK;

    const float* kbase  = g_kc + ((size_t)bh << 15);
    const float* vtbase = g_vc + ((size_t)bh << 15);

    float o[2][4][4];
    float o5[2][4];
#pragma unroll
    for (int mi = 0; mi < 2; mi++) {
#pragma unroll
        for (int nn = 0; nn < 4; nn++) {
#pragma unroll
            for (int i = 0; i < 4; i++) o[mi][nn][i] = 0.f;
            o5[mi][nn] = 0.f;
        }
    }
    uint32_t bones[2];
    bones[0] = bones[1] = (g == 0) ? 0x3F800000u : 0u;

    const int kc_c = (tid & 7) * 4;
    const int vc_c = (tid & 15) * 4;

    {
#pragma unroll
        for (int i = 0; i < 4; i++) {
            const int ek = tid + i * 128;
            const int ev = tid + i * 128;
            cp16(s2u(&Ks[0][ek >> 3][kc_c]), kbase + ((ek >> 3) << 5) + kc_c);
            cp16(s2u(&Vt[0][ev >> 4][vc_c]), vtbase + ((ev >> 4) << 10) + vc_c);
        }
        cp_commit();
    }

    for (int kt = 0; kt < 16; kt++) {
        const int cur = kt & 1;

        float s[2][2][4];
#pragma unroll
        for (int mi = 0; mi < 2; mi++)
#pragma unroll
            for (int nt = 0; nt < 2; nt++) {
                const int col = kt * 64 + nt * 8 + 2 * q;
                float2 b0 = ldg_cg2(br[mi * 2]     + col);
                float2 b1 = ldg_cg2(br[mi * 2 + 1] + col);
                s[mi][nt][0] = b0.x; s[mi][nt][1] = b0.y;
                s[mi][nt][2] = b1.x; s[mi][nt][3] = b1.y;
            }

        cp_wait0();
        __syncthreads();

        if (kt + 1 < 16) {
            const int nxt = cur ^ 1;
            const int koff = (kt + 1) * 64;
#pragma unroll
            for (int i = 0; i < 4; i++) {
                const int ek = tid + i * 128;
                const int ev = tid + i * 128;
                cp16(s2u(&Ks[nxt][ek >> 3][kc_c]),
                     kbase + ((koff + (ek >> 3)) << 5) + kc_c);
                cp16(s2u(&Vt[nxt][ev >> 4][vc_c]),
                     vtbase + ((ev >> 4) << 10) + koff + vc_c);
            }
            cp_commit();
        }

#pragma unroll
        for (int c = 0; c < 4; c++) {
            if (c > 0) {
#pragma unroll
                for (int mi = 0; mi < 2; mi++)
#pragma unroll
                    for (int nt = 0; nt < 2; nt++) {
                        const int col = kt * 64 + c * 16 + nt * 8 + 2 * q;
                        float2 b0 = ldg_cg2(br[mi * 2]     + col);
                        float2 b1 = ldg_cg2(br[mi * 2 + 1] + col);
                        s[mi][nt][0] = b0.x; s[mi][nt][1] = b0.y;
                        s[mi][nt][2] = b1.x; s[mi][nt][3] = b1.y;
                    }
            }

#pragma unroll
            for (int kk = 0; kk < 4; kk++) {
                uint32_t bf[4];
                ldsm4(bf, s2u(&Ks[cur][c * 16 + ldrow][kk * 8 + ldcol]));
#pragma unroll
                for (int mi = 0; mi < 2; mi++) {
                    mma_tf32(s[mi][0], qa[mi][kk], &bf[0]);
                    mma_tf32(s[mi][1], qa[mi][kk], &bf[2]);
                }
            }

#pragma unroll
            for (int mi = 0; mi < 2; mi++)
#pragma unroll
                for (int nt = 0; nt < 2; nt++) {
                    s[mi][nt][0] = __expf(s[mi][nt][0]);
                    s[mi][nt][1] = __expf(s[mi][nt][1]);
                    s[mi][nt][2] = __expf(s[mi][nt][2]);
                    s[mi][nt][3] = __expf(s[mi][nt][3]);
                }

#pragma unroll
            for (int nt = 0; nt < 2; nt++) {
                const int kv = c * 2 + nt;
                uint32_t v0[4], v1[4];
                ldsm4(v0, s2u(&Vt[cur][ldrow     ][kv * 8 + ldcol]));
                ldsm4(v1, s2u(&Vt[cur][16 + ldrow][kv * 8 + ldcol]));
#pragma unroll
                for (int mi = 0; mi < 2; mi++) {
                    uint32_t pa[4];
                    pa[0] = f2tf(s[mi][nt][0]);
                    pa[1] = f2tf(s[mi][nt][2]);
                    pa[2] = f2tf(s[mi][nt][1]);
                    pa[3] = f2tf(s[mi][nt][3]);
                    mma_tf32(o[mi][0], pa, &v0[0]);
                    mma_tf32(o[mi][1], pa, &v0[2]);
                    mma_tf32(o[mi][2], pa, &v1[0]);
                    mma_tf32(o[mi][3], pa, &v1[2]);
                    mma_tf32(o5[mi], pa, bones);
                }
            }
        }
    }

#pragma unroll
    for (int mi = 0; mi < 2; mi++) {
        const float l0 = __shfl_sync(0xffffffffu, o5[mi][0], lane & ~3);
        const float l1 = __shfl_sync(0xffffffffu, o5[mi][2], lane & ~3);
        const float inv0 = 1.f / l0;
        const float inv1 = 1.f / l1;
        const int row0 = rbase + mi * 16 + g;
        const int base0 = (b * NTOK + row0) * DIM + h * HD;
        const int base1 = (b * NTOK + row0 + 8) * DIM + h * HD;
#pragma unroll
        for (int nn = 0; nn < 4; nn++) {
            *(float2*)&g_mid[base0 + nn * 8 + 2 * q] = make_float2(
                __uint_as_float(f2tf(o[mi][nn][0] * inv0)),
                __uint_as_float(f2tf(o[mi][nn][1] * inv0)));
            *(float2*)&g_mid[base1 + nn * 8 + 2 * q] = make_float2(
                __uint_as_float(f2tf(o[mi][nn][2] * inv1)),
                __uint_as_float(f2tf(o[mi][nn][3] * inv1)));
        }
    }
}

// ---------------- launch ----------------
extern "C" void kernel_launch(void* const* d_in, const int* in_sizes, int n_in,
                              void* d_out, int out_size)
{
    const float* x          = (const float*)d_in[0];
    const float* w_qkv      = (const float*)d_in[1];
    const float* b_qkv      = (const float*)d_in[2];
    const float* conv_w     = (const float*)d_in[3];
    const float* conv_b     = (const float*)d_in[4];
    const float* w_proj     = (const float*)d_in[5];
    const float* b_proj     = (const float*)d_in[6];
    const float* bias_table = (const float*)d_in[7];
    float* out = (float*)d_out;

    void *pxt = nullptr, *pwq = nullptr, *pwp = nullptr, *pmid = nullptr;
    cudaGetSymbolAddress(&pxt,  g_xt);
    cudaGetSymbolAddress(&pwq,  g_wqkv);
    cudaGetSymbolAddress(&pwp,  g_wproj);
    cudaGetSymbolAddress(&pmid, g_mid);

    // 0) one-time tf32 conversion of x, w_qkv, w_proj
    cvt_pack<<<3648, 256>>>(x, w_qkv, w_proj);

    // 1) fused QKV GEMM (wide 128x128 tiles), scatter into [b,h,n,d]
    gemm_wide<3 * DIM, 0><<<dim3(9, 64), 256>>>(
        (const uint32_t*)pxt, (const uint32_t*)pwq, b_qkv, nullptr);

    // 2) depthwise 3x3 conv; K normal layout, V transposed+permuted (coalesced)
    dwconv_kernel<<<(BATCH * NH * NTOK * 8) / 256, 256>>>(conv_w, conv_b);

    // 3) tensor-core flash attention (M=32/warp) -> g_mid (tf32 bits)
    attn_mma_kernel<<<dim3(BATCH * NH, 8), 128>>>(bias_table);

    // 4) output projection (wide 128x128 tiles)
    gemm_wide<DIM, 1><<<dim3(3, 64), 256>>>(
        (const uint32_t*)pmid, (const uint32_t*)pwp, b_proj, out);
}

// round 14
// speedup vs baseline: 1.0089x; 1.0089x over previous
#include <cuda_runtime.h>
#include <math_constants.h>
#include <cstdint>

#define BATCH 8
#define NTOK  1024
#define DIM   384
#define NH    12
#define HD    32
#define QSCALE 0.17677669529663687f   // 32^-0.5

// ---------------- scratch (no allocs allowed) ----------------
// g_q, g_kc, g_vc, g_mid, g_xt, g_wqkv, g_wproj hold tf32 bit patterns
// g_vc layout: TRANSPOSED [bh][d][key'] with inner-8 key permutation
__device__ float g_q [BATCH*NH*NTOK*HD];
__device__ float g_k [BATCH*NH*NTOK*HD];
__device__ float g_v [BATCH*NH*NTOK*HD];
__device__ float g_kc[BATCH*NH*NTOK*HD];
__device__ float g_vc[BATCH*NH*NTOK*HD];
__device__ float g_mid[BATCH*NTOK*DIM];
__device__ uint32_t g_xt   [BATCH*NTOK*DIM];
__device__ uint32_t g_wqkv [DIM*3*DIM];
__device__ uint32_t g_wproj[DIM*DIM];

// ---------------- helpers ----------------
__device__ __forceinline__ uint32_t f2tf(float f) {
    uint32_t r;
    asm("cvt.rna.tf32.f32 %0, %1;" : "=r"(r) : "f"(f));
    return r;
}

__device__ __forceinline__ void mma_tf32(float c[4], const uint32_t a[4], const uint32_t b[2]) {
    asm volatile(
        "mma.sync.aligned.m16n8k8.row.col.f32.tf32.tf32.f32 "
        "{%0,%1,%2,%3},{%4,%5,%6,%7},{%8,%9},{%0,%1,%2,%3};"
        : "+f"(c[0]), "+f"(c[1]), "+f"(c[2]), "+f"(c[3])
        : "r"(a[0]), "r"(a[1]), "r"(a[2]), "r"(a[3]), "r"(b[0]), "r"(b[1]));
}

__device__ __forceinline__ uint32_t s2u(const void* p) {
    return (uint32_t)__cvta_generic_to_shared(p);
}

__device__ __forceinline__ void ldsm4(uint32_t r[4], uint32_t saddr) {
    asm volatile("ldmatrix.sync.aligned.m8n8.x4.shared.b16 {%0,%1,%2,%3}, [%4];"
        : "=r"(r[0]), "=r"(r[1]), "=r"(r[2]), "=r"(r[3]) : "r"(saddr));
}

__device__ __forceinline__ void cp16(uint32_t dst, const void* src) {
    asm volatile("cp.async.ca.shared.global [%0], [%1], 16;" :: "r"(dst), "l"(src));
}
__device__ __forceinline__ void cp_commit() {
    asm volatile("cp.async.commit_group;");
}
__device__ __forceinline__ void cp_wait0() {
    asm volatile("cp.async.wait_group 0;");
}

// ---------------- one-time tf32 pre-conversion ----------------
__global__ __launch_bounds__(256) void cvt_pack(
    const float* __restrict__ x, const float* __restrict__ wq,
    const float* __restrict__ wp)
{
    const int t = blockIdx.x * 256 + threadIdx.x;
    const float4* src;
    uint32_t* dst;
    int i;
    if (t < 786432)        { src = (const float4*)x;  dst = g_xt;    i = t; }
    else if (t < 897024)   { src = (const float4*)wq; dst = g_wqkv;  i = t - 786432; }
    else if (t < 933888)   { src = (const float4*)wp; dst = g_wproj; i = t - 897024; }
    else return;
    const float4 v = src[i];
    *(uint4*)&dst[i * 4] = make_uint4(f2tf(v.x), f2tf(v.y), f2tf(v.z), f2tf(v.w));
}

// ---------------- wide-tile GEMM: 128x128 block ----------------
// MODE 0: qkv (NDIM=1152), scatter into g_q (scaled tf32) / g_k / g_v.
// MODE 1: proj (NDIM=384), row-major float output.
template<int NDIM, int MODE>
__global__ __launch_bounds__(256, 2) void gemm_wide(
    const uint32_t* __restrict__ A, const uint32_t* __restrict__ B,
    const float* __restrict__ bias, float* __restrict__ Cout)
{
    constexpr int KDIM = 384;
    constexpr int NK   = KDIM / 16;

    __shared__ uint32_t As[2][128][20];   // [m][k]
    __shared__ uint32_t Bs[2][128][20];   // [n][k]

    const int m0  = blockIdx.y * 128;
    const int n0  = blockIdx.x * 128;
    const int tid  = threadIdx.x;
    const int warp = tid >> 5;
    const int lane = tid & 31;
    const int g = lane >> 2;
    const int q = lane & 3;
    const int wm = (warp & 3) * 32;
    const int wn = (warp >> 2) * 64;

    const int ldrow = (lane & 7) | ((lane & 16) >> 1);
    const int ldcol = ((lane >> 3) & 1) * 4;

    const int ar0 = (tid)       >> 2, ak0 = ((tid)       & 3) * 4;
    const int ar1 = (tid + 256) >> 2, ak1 = ((tid + 256) & 3) * 4;
    const int bn   = tid & 127;
    const int bkq0 = (tid >> 7) * 4;

    float acc[2][8][4];
#pragma unroll
    for (int mi = 0; mi < 2; mi++)
#pragma unroll
        for (int ni = 0; ni < 8; ni++)
#pragma unroll
            for (int i = 0; i < 4; i++) acc[mi][ni][i] = 0.f;

    uint32_t pb[2][4];

    cp16(s2u(&As[0][ar0][ak0]), A + (size_t)(m0 + ar0) * KDIM + ak0);
    cp16(s2u(&As[0][ar1][ak1]), A + (size_t)(m0 + ar1) * KDIM + ak1);
    cp_commit();
#pragma unroll
    for (int i = 0; i < 2; i++)
#pragma unroll
        for (int j = 0; j < 4; j++)
            pb[i][j] = B[(size_t)(bkq0 + i * 8 + j) * NDIM + n0 + bn];
#pragma unroll
    for (int i = 0; i < 2; i++)
        *(uint4*)&Bs[0][bn][bkq0 + i * 8] =
            make_uint4(pb[i][0], pb[i][1], pb[i][2], pb[i][3]);
    cp_wait0();
    __syncthreads();

    for (int kb = 0; kb < NK; kb++) {
        const int  cur      = kb & 1;
        const bool has_next = (kb + 1) < NK;
        const int  nxt      = cur ^ 1;

        if (has_next) {
            const int k0 = (kb + 1) * 16;
#pragma unroll
            for (int i = 0; i < 2; i++)
#pragma unroll
                for (int j = 0; j < 4; j++)
                    pb[i][j] = B[(size_t)(k0 + bkq0 + i * 8 + j) * NDIM + n0 + bn];
            cp16(s2u(&As[nxt][ar0][ak0]), A + (size_t)(m0 + ar0) * KDIM + k0 + ak0);
            cp16(s2u(&As[nxt][ar1][ak1]), A + (size_t)(m0 + ar1) * KDIM + k0 + ak1);
            cp_commit();
        }

#pragma unroll
        for (int s = 0; s < 2; s++) {
            uint32_t af[2][4], bf4[4][4];
#pragma unroll
            for (int mi = 0; mi < 2; mi++) {
                uint32_t r[4];
                ldsm4(r, s2u(&As[cur][wm + mi * 16 + ldrow][s * 8 + ldcol]));
                af[mi][0] = r[0]; af[mi][1] = r[2];
                af[mi][2] = r[1]; af[mi][3] = r[3];
            }
#pragma unroll
            for (int nj = 0; nj < 4; nj++)
                ldsm4(bf4[nj], s2u(&Bs[cur][wn + nj * 16 + ldrow][s * 8 + ldcol]));
#pragma unroll
            for (int mi = 0; mi < 2; mi++)
#pragma unroll
                for (int ni = 0; ni < 8; ni++)
                    mma_tf32(acc[mi][ni], af[mi], &bf4[ni >> 1][(ni & 1) * 2]);
        }

        if (has_next) {
#pragma unroll
            for (int i = 0; i < 2; i++)
                *(uint4*)&Bs[nxt][bn][bkq0 + i * 8] =
                    make_uint4(pb[i][0], pb[i][1], pb[i][2], pb[i][3]);
            cp_wait0();
        }
        __syncthreads();
    }

#pragma unroll
    for (int mi = 0; mi < 2; mi++) {
#pragma unroll
        for (int rr = 0; rr < 2; rr++) {
            const int row  = m0 + wm + mi * 16 + g + rr * 8;
            const int bidx = row >> 10;
            const int n    = row & 1023;
#pragma unroll
            for (int ni = 0; ni < 8; ni++) {
                const int col = n0 + wn + ni * 8 + 2 * q;
                const float v0 = acc[mi][ni][rr * 2]     + bias[col];
                const float v1 = acc[mi][ni][rr * 2 + 1] + bias[col + 1];
                if (MODE == 0) {
                    const int s = col / DIM;
                    const int r = col - s * DIM;
                    const int h = r >> 5;
                    const int d = r & 31;
                    const int off = (((bidx * NH + h) * NTOK + n) << 5) + d;
                    if (s == 0) {
                        *(float2*)&g_q[off] = make_float2(
                            __uint_as_float(f2tf(v0 * QSCALE)),
                            __uint_as_float(f2tf(v1 * QSCALE)));
                    } else {
                        float* dst = (s == 1) ? g_k : g_v;
                        *(float2*)&dst[off] = make_float2(v0, v1);
                    }
                } else {
                    *(float2*)&Cout[(size_t)row * NDIM + col] = make_float2(v0, v1);
                }
            }
        }
    }
}

// ---------------- depthwise 3x3 SAME conv on K and V ----------------
// K written [bh][key][d] (tf32), coalesced. V written TRANSPOSED
// [bh][d][key'] (tf32, inner-8 perm) via smem transpose (coalesced stores).
__global__ __launch_bounds__(256) void dwconv_kernel(
    const float* __restrict__ w, const float* __restrict__ cb)
{
    __shared__ float sv[32][33];

    const int t   = blockIdx.x * 256 + threadIdx.x;
    const int d4  = (t & 7) * 4;
    const int n   = (t >> 3) & 1023;
    const int img = t >> 13;
    const int y = n >> 5, x = n & 31;
    const int base = img << 15;

    float4 wr[9];
#pragma unroll
    for (int j = 0; j < 9; j++)
        wr[j] = make_float4(w[(d4 + 0) * 9 + j], w[(d4 + 1) * 9 + j],
                            w[(d4 + 2) * 9 + j], w[(d4 + 3) * 9 + j]);

    float4 aK = *(const float4*)&cb[d4];
    float4 aV = aK;
#pragma unroll
    for (int ky = 0; ky < 3; ky++) {
        const int yy = y + ky - 1;
        if (yy < 0 || yy > 31) continue;
#pragma unroll
        for (int kx = 0; kx < 3; kx++) {
            const int xx = x + kx - 1;
            if (xx < 0 || xx > 31) continue;
            const float4 wv = wr[ky * 3 + kx];
            const int off = base + (((yy << 5) | xx) << 5) + d4;
            const float4 kv = *(const float4*)&g_k[off];
            const float4 vv = *(const float4*)&g_v[off];
            aK.x += kv.x * wv.x; aK.y += kv.y * wv.y;
            aK.z += kv.z * wv.z; aK.w += kv.w * wv.w;
            aV.x += vv.x * wv.x; aV.y += vv.y * wv.y;
            aV.z += vv.z * wv.z; aV.w += vv.w * wv.w;
        }
    }
    const int out = base + (n << 5) + d4;
    *(float4*)&g_kc[out] = make_float4(
        __uint_as_float(f2tf(aK.x)), __uint_as_float(f2tf(aK.y)),
        __uint_as_float(f2tf(aK.z)), __uint_as_float(f2tf(aK.w)));

    const int nl = n & 31;
    sv[d4 + 0][nl] = __uint_as_float(f2tf(aV.x));
    sv[d4 + 1][nl] = __uint_as_float(f2tf(aV.y));
    sv[d4 + 2][nl] = __uint_as_float(f2tf(aV.z));
    sv[d4 + 3][nl] = __uint_as_float(f2tf(aV.w));
    __syncthreads();

    const int lane  = t & 31;
    const int wid   = (threadIdx.x >> 5) & 7;
    const int nbase = n & ~31;
    const int j     = lane & 7;
    const int nper  = (lane & ~7) | ((j & 1) ? (4 + (j >> 1)) : (j >> 1));
#pragma unroll
    for (int r = 0; r < 4; r++) {
        const int dd = wid * 4 + r;
        g_vc[base + (dd << 10) + nbase + nper] = sv[dd][lane];
    }
}

// ---------------- flash attention: M=32 per warp, shared K/V fragments ----
// grid (96, 8): (b*NH h-major, 128-query tile). 128 threads = 4 warps x 32
// rows. Fixed-max softmax; l via ones-column MMA. P fed to the tf32 MMA as
// raw fp32 bits (HW reads top 19 bits = truncation) -- removes 64 F2FP ops
// per tile per thread from the exp->MMA critical chain. The ones-column
// l-MMA uses the SAME pa registers, so numerator/denominator shift together.
__global__ __launch_bounds__(128, 3) void attn_mma_kernel(const float* __restrict__ bias)
{
    __shared__ uint32_t Ks[2][64][36];   // [key][d]
    __shared__ uint32_t Vt[2][32][68];   // [d][key'] -- GEMM-B layout

    const int bhx = blockIdx.x;
    const int qt  = blockIdx.y;
    const int h   = bhx >> 3;
    const int b   = bhx & 7;
    const int bh  = b * NH + h;
    const int tid  = threadIdx.x;
    const int warp = tid >> 5;
    const int lane = tid & 31;
    const int g = lane >> 2;
    const int q = lane & 3;

    const int ldrow = (lane & 7) | ((lane & 16) >> 1);
    const int ldcol = ((lane >> 3) & 1) * 4;

    const int rbase = qt * 128 + warp * 32;

    uint32_t qa[2][4][4];
#pragma unroll
    for (int mi = 0; mi < 2; mi++) {
        const float* q0 = g_q + ((bh * NTOK + rbase + mi * 16 + g) << 5);
        const float* q1 = q0 + (8 << 5);
#pragma unroll
        for (int kk = 0; kk < 4; kk++) {
            qa[mi][kk][0] = __float_as_uint(q0[kk * 8 + q]);
            qa[mi][kk][1] = __float_as_uint(q1[kk * 8 + q]);
            qa[mi][kk][2] = __float_as_uint(q0[kk * 8 + q + 4]);
            qa[mi][kk][3] = __float_as_uint(q1[kk * 8 + q + 4]);
        }
    }

    const float* br[4];
#pragma unroll
    for (int i = 0; i < 4; i++)
        br[i] = bias + ((size_t)h * NTOK + rbase + i * 8 + g) * NTOK;

    const float* kbase  = g_kc + ((size_t)bh << 15);
    const float* vtbase = g_vc + ((size_t)bh << 15);

    float o[2][4][4];
    float o5[2][4];
#pragma unroll
    for (int mi = 0; mi < 2; mi++) {
#pragma unroll
        for (int nn = 0; nn < 4; nn++) {
#pragma unroll
            for (int i = 0; i < 4; i++) o[mi][nn][i] = 0.f;
            o5[mi][nn] = 0.f;
        }
    }
    uint32_t bones[2];
    bones[0] = bones[1] = (g == 0) ? 0x3F800000u : 0u;

    const int kc_c = (tid & 7) * 4;
    const int vc_c = (tid & 15) * 4;

    {
#pragma unroll
        for (int i = 0; i < 4; i++) {
            const int ek = tid + i * 128;
            const int ev = tid + i * 128;
            cp16(s2u(&Ks[0][ek >> 3][kc_c]), kbase + ((ek >> 3) << 5) + kc_c);
            cp16(s2u(&Vt[0][ev >> 4][vc_c]), vtbase + ((ev >> 4) << 10) + vc_c);
        }
        cp_commit();
    }

    for (int kt = 0; kt < 16; kt++) {
        const int cur = kt & 1;

        float s[2][2][4];
#pragma unroll
        for (int mi = 0; mi < 2; mi++)
#pragma unroll
            for (int nt = 0; nt < 2; nt++) {
                const int col = kt * 64 + nt * 8 + 2 * q;
                float2 b0 = *(const float2*)(br[mi * 2]     + col);
                float2 b1 = *(const float2*)(br[mi * 2 + 1] + col);
                s[mi][nt][0] = b0.x; s[mi][nt][1] = b0.y;
                s[mi][nt][2] = b1.x; s[mi][nt][3] = b1.y;
            }

        cp_wait0();
        __syncthreads();

        if (kt + 1 < 16) {
            const int nxt = cur ^ 1;
            const int koff = (kt + 1) * 64;
#pragma unroll
            for (int i = 0; i < 4; i++) {
                const int ek = tid + i * 128;
                const int ev = tid + i * 128;
                cp16(s2u(&Ks[nxt][ek >> 3][kc_c]),
                     kbase + ((koff + (ek >> 3)) << 5) + kc_c);
                cp16(s2u(&Vt[nxt][ev >> 4][vc_c]),
                     vtbase + ((ev >> 4) << 10) + koff + vc_c);
            }
            cp_commit();
        }

#pragma unroll
        for (int c = 0; c < 4; c++) {
            if (c > 0) {
#pragma unroll
                for (int mi = 0; mi < 2; mi++)
#pragma unroll
                    for (int nt = 0; nt < 2; nt++) {
                        const int col = kt * 64 + c * 16 + nt * 8 + 2 * q;
                        float2 b0 = *(const float2*)(br[mi * 2]     + col);
                        float2 b1 = *(const float2*)(br[mi * 2 + 1] + col);
                        s[mi][nt][0] = b0.x; s[mi][nt][1] = b0.y;
                        s[mi][nt][2] = b1.x; s[mi][nt][3] = b1.y;
                    }
            }

#pragma unroll
            for (int kk = 0; kk < 4; kk++) {
                uint32_t bf[4];
                ldsm4(bf, s2u(&Ks[cur][c * 16 + ldrow][kk * 8 + ldcol]));
#pragma unroll
                for (int mi = 0; mi < 2; mi++) {
                    mma_tf32(s[mi][0], qa[mi][kk], &bf[0]);
                    mma_tf32(s[mi][1], qa[mi][kk], &bf[2]);
                }
            }

#pragma unroll
            for (int mi = 0; mi < 2; mi++)
#pragma unroll
                for (int nt = 0; nt < 2; nt++) {
                    s[mi][nt][0] = __expf(s[mi][nt][0]);
                    s[mi][nt][1] = __expf(s[mi][nt][1]);
                    s[mi][nt][2] = __expf(s[mi][nt][2]);
                    s[mi][nt][3] = __expf(s[mi][nt][3]);
                }

#pragma unroll
            for (int nt = 0; nt < 2; nt++) {
                const int kv = c * 2 + nt;
                uint32_t v0[4], v1[4];
                ldsm4(v0, s2u(&Vt[cur][ldrow     ][kv * 8 + ldcol]));
                ldsm4(v1, s2u(&Vt[cur][16 + ldrow][kv * 8 + ldcol]));
#pragma unroll
                for (int mi = 0; mi < 2; mi++) {
                    uint32_t pa[4];
                    pa[0] = __float_as_uint(s[mi][nt][0]);
                    pa[1] = __float_as_uint(s[mi][nt][2]);
                    pa[2] = __float_as_uint(s[mi][nt][1]);
                    pa[3] = __float_as_uint(s[mi][nt][3]);
                    mma_tf32(o[mi][0], pa, &v0[0]);
                    mma_tf32(o[mi][1], pa, &v0[2]);
                    mma_tf32(o[mi][2], pa, &v1[0]);
                    mma_tf32(o[mi][3], pa, &v1[2]);
                    mma_tf32(o5[mi], pa, bones);
                }
            }
        }
    }

#pragma unroll
    for (int mi = 0; mi < 2; mi++) {
        const float l0 = __shfl_sync(0xffffffffu, o5[mi][0], lane & ~3);
        const float l1 = __shfl_sync(0xffffffffu, o5[mi][2], lane & ~3);
        const float inv0 = 1.f / l0;
        const float inv1 = 1.f / l1;
        const int row0 = rbase + mi * 16 + g;
        const int base0 = (b * NTOK + row0) * DIM + h * HD;
        const int base1 = (b * NTOK + row0 + 8) * DIM + h * HD;
#pragma unroll
        for (int nn = 0; nn < 4; nn++) {
            *(float2*)&g_mid[base0 + nn * 8 + 2 * q] = make_float2(
                __uint_as_float(f2tf(o[mi][nn][0] * inv0)),
                __uint_as_float(f2tf(o[mi][nn][1] * inv0)));
            *(float2*)&g_mid[base1 + nn * 8 + 2 * q] = make_float2(
                __uint_as_float(f2tf(o[mi][nn][2] * inv1)),
                __uint_as_float(f2tf(o[mi][nn][3] * inv1)));
        }
    }
}

// ---------------- launch ----------------
extern "C" void kernel_launch(void* const* d_in, const int* in_sizes, int n_in,
                              void* d_out, int out_size)
{
    const float* x          = (const float*)d_in[0];
    const float* w_qkv      = (const float*)d_in[1];
    const float* b_qkv      = (const float*)d_in[2];
    const float* conv_w     = (const float*)d_in[3];
    const float* conv_b     = (const float*)d_in[4];
    const float* w_proj     = (const float*)d_in[5];
    const float* b_proj     = (const float*)d_in[6];
    const float* bias_table = (const float*)d_in[7];
    float* out = (float*)d_out;

    void *pxt = nullptr, *pwq = nullptr, *pwp = nullptr, *pmid = nullptr;
    cudaGetSymbolAddress(&pxt,  g_xt);
    cudaGetSymbolAddress(&pwq,  g_wqkv);
    cudaGetSymbolAddress(&pwp,  g_wproj);
    cudaGetSymbolAddress(&pmid, g_mid);

    // 0) one-time tf32 conversion of x, w_qkv, w_proj
    cvt_pack<<<3648, 256>>>(x, w_qkv, w_proj);

    // 1) fused QKV GEMM (wide 128x128 tiles), scatter into [b,h,n,d]
    gemm_wide<3 * DIM, 0><<<dim3(9, 64), 256>>>(
        (const uint32_t*)pxt, (const uint32_t*)pwq, b_qkv, nullptr);

    // 2) depthwise 3x3 conv; K normal layout, V transposed+permuted (coalesced)
    dwconv_kernel<<<(BATCH * NH * NTOK * 8) / 256, 256>>>(conv_w, conv_b);

    // 3) tensor-core flash attention (M=32/warp) -> g_mid (tf32 bits)
    attn_mma_kernel<<<dim3(BATCH * NH, 8), 128>>>(bias_table);

    // 4) output projection (wide 128x128 tiles)
    gemm_wide<DIM, 1><<<dim3(3, 64), 256>>>(
        (const uint32_t*)pmid, (const uint32_t*)pwp, b_proj, out);
}

// round 15
// speedup vs baseline: 1.0266x; 1.0175x over previous
#include <cuda_runtime.h>
#include <math_constants.h>
#include <cstdint>

#define BATCH 8
#define NTOK  1024
#define DIM   384
#define NH    12
#define HD    32
#define QSCALE 0.17677669529663687f            // 32^-0.5
#define LOG2E  1.4426950408889634f
#define QLSCALE (QSCALE * LOG2E)               // folded: scores in log2 domain

// ---------------- scratch (no allocs allowed) ----------------
// g_q, g_kc, g_vc, g_mid, g_xt, g_wqkv, g_wproj hold tf32 bit patterns
// g_q is pre-scaled by QSCALE*log2e (softmax computed in base 2)
// g_vc layout: TRANSPOSED [bh][d][key'] with inner-8 key permutation
__device__ float g_q [BATCH*NH*NTOK*HD];
__device__ float g_k [BATCH*NH*NTOK*HD];
__device__ float g_v [BATCH*NH*NTOK*HD];
__device__ float g_kc[BATCH*NH*NTOK*HD];
__device__ float g_vc[BATCH*NH*NTOK*HD];
__device__ float g_mid[BATCH*NTOK*DIM];
__device__ uint32_t g_xt   [BATCH*NTOK*DIM];
__device__ uint32_t g_wqkv [DIM*3*DIM];
__device__ uint32_t g_wproj[DIM*DIM];

// ---------------- helpers ----------------
__device__ __forceinline__ uint32_t f2tf(float f) {
    uint32_t r;
    asm("cvt.rna.tf32.f32 %0, %1;" : "=r"(r) : "f"(f));
    return r;
}

__device__ __forceinline__ float ex2f(float x) {
    float r;
    asm("ex2.approx.ftz.f32 %0, %1;" : "=f"(r) : "f"(x));
    return r;
}

__device__ __forceinline__ void mma_tf32(float c[4], const uint32_t a[4], const uint32_t b[2]) {
    asm volatile(
        "mma.sync.aligned.m16n8k8.row.col.f32.tf32.tf32.f32 "
        "{%0,%1,%2,%3},{%4,%5,%6,%7},{%8,%9},{%0,%1,%2,%3};"
        : "+f"(c[0]), "+f"(c[1]), "+f"(c[2]), "+f"(c[3])
        : "r"(a[0]), "r"(a[1]), "r"(a[2]), "r"(a[3]), "r"(b[0]), "r"(b[1]));
}

__device__ __forceinline__ uint32_t s2u(const void* p) {
    return (uint32_t)__cvta_generic_to_shared(p);
}

__device__ __forceinline__ void ldsm4(uint32_t r[4], uint32_t saddr) {
    asm volatile("ldmatrix.sync.aligned.m8n8.x4.shared.b16 {%0,%1,%2,%3}, [%4];"
        : "=r"(r[0]), "=r"(r[1]), "=r"(r[2]), "=r"(r[3]) : "r"(saddr));
}

__device__ __forceinline__ void cp16(uint32_t dst, const void* src) {
    asm volatile("cp.async.ca.shared.global [%0], [%1], 16;" :: "r"(dst), "l"(src));
}
__device__ __forceinline__ void cp_commit() {
    asm volatile("cp.async.commit_group;");
}
__device__ __forceinline__ void cp_wait0() {
    asm volatile("cp.async.wait_group 0;");
}

// ---------------- one-time tf32 pre-conversion ----------------
__global__ __launch_bounds__(256) void cvt_pack(
    const float* __restrict__ x, const float* __restrict__ wq,
    const float* __restrict__ wp)
{
    const int t = blockIdx.x * 256 + threadIdx.x;
    const float4* src;
    uint32_t* dst;
    int i;
    if (t < 786432)        { src = (const float4*)x;  dst = g_xt;    i = t; }
    else if (t < 897024)   { src = (const float4*)wq; dst = g_wqkv;  i = t - 786432; }
    else if (t < 933888)   { src = (const float4*)wp; dst = g_wproj; i = t - 897024; }
    else return;
    const float4 v = src[i];
    *(uint4*)&dst[i * 4] = make_uint4(f2tf(v.x), f2tf(v.y), f2tf(v.z), f2tf(v.w));
}

// ---------------- wide-tile GEMM: 128x128 block ----------------
// MODE 0: qkv (NDIM=1152), scatter into g_q (scaled tf32) / g_k / g_v.
// MODE 1: proj (NDIM=384), row-major float output.
template<int NDIM, int MODE>
__global__ __launch_bounds__(256, 2) void gemm_wide(
    const uint32_t* __restrict__ A, const uint32_t* __restrict__ B,
    const float* __restrict__ bias, float* __restrict__ Cout)
{
    constexpr int KDIM = 384;
    constexpr int NK   = KDIM / 16;

    __shared__ uint32_t As[2][128][20];   // [m][k]
    __shared__ uint32_t Bs[2][128][20];   // [n][k]

    const int m0  = blockIdx.y * 128;
    const int n0  = blockIdx.x * 128;
    const int tid  = threadIdx.x;
    const int warp = tid >> 5;
    const int lane = tid & 31;
    const int g = lane >> 2;
    const int q = lane & 3;
    const int wm = (warp & 3) * 32;
    const int wn = (warp >> 2) * 64;

    const int ldrow = (lane & 7) | ((lane & 16) >> 1);
    const int ldcol = ((lane >> 3) & 1) * 4;

    const int ar0 = (tid)       >> 2, ak0 = ((tid)       & 3) * 4;
    const int ar1 = (tid + 256) >> 2, ak1 = ((tid + 256) & 3) * 4;
    const int bn   = tid & 127;
    const int bkq0 = (tid >> 7) * 4;

    float acc[2][8][4];
#pragma unroll
    for (int mi = 0; mi < 2; mi++)
#pragma unroll
        for (int ni = 0; ni < 8; ni++)
#pragma unroll
            for (int i = 0; i < 4; i++) acc[mi][ni][i] = 0.f;

    uint32_t pb[2][4];

    cp16(s2u(&As[0][ar0][ak0]), A + (size_t)(m0 + ar0) * KDIM + ak0);
    cp16(s2u(&As[0][ar1][ak1]), A + (size_t)(m0 + ar1) * KDIM + ak1);
    cp_commit();
#pragma unroll
    for (int i = 0; i < 2; i++)
#pragma unroll
        for (int j = 0; j < 4; j++)
            pb[i][j] = B[(size_t)(bkq0 + i * 8 + j) * NDIM + n0 + bn];
#pragma unroll
    for (int i = 0; i < 2; i++)
        *(uint4*)&Bs[0][bn][bkq0 + i * 8] =
            make_uint4(pb[i][0], pb[i][1], pb[i][2], pb[i][3]);
    cp_wait0();
    __syncthreads();

    for (int kb = 0; kb < NK; kb++) {
        const int  cur      = kb & 1;
        const bool has_next = (kb + 1) < NK;
        const int  nxt      = cur ^ 1;

        if (has_next) {
            const int k0 = (kb + 1) * 16;
#pragma unroll
            for (int i = 0; i < 2; i++)
#pragma unroll
                for (int j = 0; j < 4; j++)
                    pb[i][j] = B[(size_t)(k0 + bkq0 + i * 8 + j) * NDIM + n0 + bn];
            cp16(s2u(&As[nxt][ar0][ak0]), A + (size_t)(m0 + ar0) * KDIM + k0 + ak0);
            cp16(s2u(&As[nxt][ar1][ak1]), A + (size_t)(m0 + ar1) * KDIM + k0 + ak1);
            cp_commit();
        }

#pragma unroll
        for (int s = 0; s < 2; s++) {
            uint32_t af[2][4], bf4[4][4];
#pragma unroll
            for (int mi = 0; mi < 2; mi++) {
                uint32_t r[4];
                ldsm4(r, s2u(&As[cur][wm + mi * 16 + ldrow][s * 8 + ldcol]));
                af[mi][0] = r[0]; af[mi][1] = r[2];
                af[mi][2] = r[1]; af[mi][3] = r[3];
            }
#pragma unroll
            for (int nj = 0; nj < 4; nj++)
                ldsm4(bf4[nj], s2u(&Bs[cur][wn + nj * 16 + ldrow][s * 8 + ldcol]));
#pragma unroll
            for (int mi = 0; mi < 2; mi++)
#pragma unroll
                for (int ni = 0; ni < 8; ni++)
                    mma_tf32(acc[mi][ni], af[mi], &bf4[ni >> 1][(ni & 1) * 2]);
        }

        if (has_next) {
#pragma unroll
            for (int i = 0; i < 2; i++)
                *(uint4*)&Bs[nxt][bn][bkq0 + i * 8] =
                    make_uint4(pb[i][0], pb[i][1], pb[i][2], pb[i][3]);
            cp_wait0();
        }
        __syncthreads();
    }

#pragma unroll
    for (int mi = 0; mi < 2; mi++) {
#pragma unroll
        for (int rr = 0; rr < 2; rr++) {
            const int row  = m0 + wm + mi * 16 + g + rr * 8;
            const int bidx = row >> 10;
            const int n    = row & 1023;
#pragma unroll
            for (int ni = 0; ni < 8; ni++) {
                const int col = n0 + wn + ni * 8 + 2 * q;
                const float v0 = acc[mi][ni][rr * 2]     + bias[col];
                const float v1 = acc[mi][ni][rr * 2 + 1] + bias[col + 1];
                if (MODE == 0) {
                    const int s = col / DIM;
                    const int r = col - s * DIM;
                    const int h = r >> 5;
                    const int d = r & 31;
                    const int off = (((bidx * NH + h) * NTOK + n) << 5) + d;
                    if (s == 0) {
                        *(float2*)&g_q[off] = make_float2(
                            __uint_as_float(f2tf(v0 * QLSCALE)),
                            __uint_as_float(f2tf(v1 * QLSCALE)));
                    } else {
                        float* dst = (s == 1) ? g_k : g_v;
                        *(float2*)&dst[off] = make_float2(v0, v1);
                    }
                } else {
                    *(float2*)&Cout[(size_t)row * NDIM + col] = make_float2(v0, v1);
                }
            }
        }
    }
}

// ---------------- depthwise 3x3 SAME conv on K and V ----------------
// K written [bh][key][d] (tf32), coalesced. V written TRANSPOSED
// [bh][d][key'] (tf32, inner-8 perm) via smem transpose (coalesced stores).
__global__ __launch_bounds__(256) void dwconv_kernel(
    const float* __restrict__ w, const float* __restrict__ cb)
{
    __shared__ float sv[32][33];

    const int t   = blockIdx.x * 256 + threadIdx.x;
    const int d4  = (t & 7) * 4;
    const int n   = (t >> 3) & 1023;
    const int img = t >> 13;
    const int y = n >> 5, x = n & 31;
    const int base = img << 15;

    float4 wr[9];
#pragma unroll
    for (int j = 0; j < 9; j++)
        wr[j] = make_float4(w[(d4 + 0) * 9 + j], w[(d4 + 1) * 9 + j],
                            w[(d4 + 2) * 9 + j], w[(d4 + 3) * 9 + j]);

    float4 aK = *(const float4*)&cb[d4];
    float4 aV = aK;
#pragma unroll
    for (int ky = 0; ky < 3; ky++) {
        const int yy = y + ky - 1;
        if (yy < 0 || yy > 31) continue;
#pragma unroll
        for (int kx = 0; kx < 3; kx++) {
            const int xx = x + kx - 1;
            if (xx < 0 || xx > 31) continue;
            const float4 wv = wr[ky * 3 + kx];
            const int off = base + (((yy << 5) | xx) << 5) + d4;
            const float4 kv = *(const float4*)&g_k[off];
            const float4 vv = *(const float4*)&g_v[off];
            aK.x += kv.x * wv.x; aK.y += kv.y * wv.y;
            aK.z += kv.z * wv.z; aK.w += kv.w * wv.w;
            aV.x += vv.x * wv.x; aV.y += vv.y * wv.y;
            aV.z += vv.z * wv.z; aV.w += vv.w * wv.w;
        }
    }
    const int out = base + (n << 5) + d4;
    *(float4*)&g_kc[out] = make_float4(
        __uint_as_float(f2tf(aK.x)), __uint_as_float(f2tf(aK.y)),
        __uint_as_float(f2tf(aK.z)), __uint_as_float(f2tf(aK.w)));

    const int nl = n & 31;
    sv[d4 + 0][nl] = __uint_as_float(f2tf(aV.x));
    sv[d4 + 1][nl] = __uint_as_float(f2tf(aV.y));
    sv[d4 + 2][nl] = __uint_as_float(f2tf(aV.z));
    sv[d4 + 3][nl] = __uint_as_float(f2tf(aV.w));
    __syncthreads();

    const int lane  = t & 31;
    const int wid   = (threadIdx.x >> 5) & 7;
    const int nbase = n & ~31;
    const int j     = lane & 7;
    const int nper  = (lane & ~7) | ((j & 1) ? (4 + (j >> 1)) : (j >> 1));
#pragma unroll
    for (int r = 0; r < 4; r++) {
        const int dd = wid * 4 + r;
        g_vc[base + (dd << 10) + nbase + nper] = sv[dd][lane];
    }
}

// ---------------- flash attention: base-2 softmax, M=32 per warp ----------
// grid (96, 8): (b*NH h-major, 128-query tile). 128 threads = 4 warps x 32
// rows. Scores accumulate in log2 domain (Q pre-scaled by QSCALE*log2e,
// bias scaled by log2e at init -- off the critical chain), so the exp is a
// bare MUFU ex2 with no FMUL on the MMA->exp->MMA path. P fed to the MMA as
// raw fp32 bits (tf32 truncation); l via ones-column MMA on the same pa.
__global__ __launch_bounds__(128, 3) void attn_mma_kernel(const float* __restrict__ bias)
{
    __shared__ uint32_t Ks[2][64][36];   // [key][d]
    __shared__ uint32_t Vt[2][32][68];   // [d][key'] -- GEMM-B layout

    const int bhx = blockIdx.x;
    const int qt  = blockIdx.y;
    const int h   = bhx >> 3;
    const int b   = bhx & 7;
    const int bh  = b * NH + h;
    const int tid  = threadIdx.x;
    const int warp = tid >> 5;
    const int lane = tid & 31;
    const int g = lane >> 2;
    const int q = lane & 3;

    const int ldrow = (lane & 7) | ((lane & 16) >> 1);
    const int ldcol = ((lane >> 3) & 1) * 4;

    const int rbase = qt * 128 + warp * 32;

    uint32_t qa[2][4][4];
#pragma unroll
    for (int mi = 0; mi < 2; mi++) {
        const float* q0 = g_q + ((bh * NTOK + rbase + mi * 16 + g) << 5);
        const float* q1 = q0 + (8 << 5);
#pragma unroll
        for (int kk = 0; kk < 4; kk++) {
            qa[mi][kk][0] = __float_as_uint(q0[kk * 8 + q]);
            qa[mi][kk][1] = __float_as_uint(q1[kk * 8 + q]);
            qa[mi][kk][2] = __float_as_uint(q0[kk * 8 + q + 4]);
            qa[mi][kk][3] = __float_as_uint(q1[kk * 8 + q + 4]);
        }
    }

    const float* br[4];
#pragma unroll
    for (int i = 0; i < 4; i++)
        br[i] = bias + ((size_t)h * NTOK + rbase + i * 8 + g) * NTOK;

    const float* kbase  = g_kc + ((size_t)bh << 15);
    const float* vtbase = g_vc + ((size_t)bh << 15);

    float o[2][4][4];
    float o5[2][4];
#pragma unroll
    for (int mi = 0; mi < 2; mi++) {
#pragma unroll
        for (int nn = 0; nn < 4; nn++) {
#pragma unroll
            for (int i = 0; i < 4; i++) o[mi][nn][i] = 0.f;
            o5[mi][nn] = 0.f;
        }
    }
    uint32_t bones[2];
    bones[0] = bones[1] = (g == 0) ? 0x3F800000u : 0u;

    const int kc_c = (tid & 7) * 4;
    const int vc_c = (tid & 15) * 4;

    {
#pragma unroll
        for (int i = 0; i < 4; i++) {
            const int ek = tid + i * 128;
            const int ev = tid + i * 128;
            cp16(s2u(&Ks[0][ek >> 3][kc_c]), kbase + ((ek >> 3) << 5) + kc_c);
            cp16(s2u(&Vt[0][ev >> 4][vc_c]), vtbase + ((ev >> 4) << 10) + vc_c);
        }
        cp_commit();
    }

    for (int kt = 0; kt < 16; kt++) {
        const int cur = kt & 1;

        float s[2][2][4];
#pragma unroll
        for (int mi = 0; mi < 2; mi++)
#pragma unroll
            for (int nt = 0; nt < 2; nt++) {
                const int col = kt * 64 + nt * 8 + 2 * q;
                float2 b0 = *(const float2*)(br[mi * 2]     + col);
                float2 b1 = *(const float2*)(br[mi * 2 + 1] + col);
                s[mi][nt][0] = b0.x * LOG2E; s[mi][nt][1] = b0.y * LOG2E;
                s[mi][nt][2] = b1.x * LOG2E; s[mi][nt][3] = b1.y * LOG2E;
            }

        cp_wait0();
        __syncthreads();

        if (kt + 1 < 16) {
            const int nxt = cur ^ 1;
            const int koff = (kt + 1) * 64;
#pragma unroll
            for (int i = 0; i < 4; i++) {
                const int ek = tid + i * 128;
                const int ev = tid + i * 128;
                cp16(s2u(&Ks[nxt][ek >> 3][kc_c]),
                     kbase + ((koff + (ek >> 3)) << 5) + kc_c);
                cp16(s2u(&Vt[nxt][ev >> 4][vc_c]),
                     vtbase + ((ev >> 4) << 10) + koff + vc_c);
            }
            cp_commit();
        }

#pragma unroll
        for (int c = 0; c < 4; c++) {
            if (c > 0) {
#pragma unroll
                for (int mi = 0; mi < 2; mi++)
#pragma unroll
                    for (int nt = 0; nt < 2; nt++) {
                        const int col = kt * 64 + c * 16 + nt * 8 + 2 * q;
                        float2 b0 = *(const float2*)(br[mi * 2]     + col);
                        float2 b1 = *(const float2*)(br[mi * 2 + 1] + col);
                        s[mi][nt][0] = b0.x * LOG2E; s[mi][nt][1] = b0.y * LOG2E;
                        s[mi][nt][2] = b1.x * LOG2E; s[mi][nt][3] = b1.y * LOG2E;
                    }
            }

#pragma unroll
            for (int kk = 0; kk < 4; kk++) {
                uint32_t bf[4];
                ldsm4(bf, s2u(&Ks[cur][c * 16 + ldrow][kk * 8 + ldcol]));
#pragma unroll
                for (int mi = 0; mi < 2; mi++) {
                    mma_tf32(s[mi][0], qa[mi][kk], &bf[0]);
                    mma_tf32(s[mi][1], qa[mi][kk], &bf[2]);
                }
            }

#pragma unroll
            for (int mi = 0; mi < 2; mi++)
#pragma unroll
                for (int nt = 0; nt < 2; nt++) {
                    s[mi][nt][0] = ex2f(s[mi][nt][0]);
                    s[mi][nt][1] = ex2f(s[mi][nt][1]);
                    s[mi][nt][2] = ex2f(s[mi][nt][2]);
                    s[mi][nt][3] = ex2f(s[mi][nt][3]);
                }

#pragma unroll
            for (int nt = 0; nt < 2; nt++) {
                const int kv = c * 2 + nt;
                uint32_t v0[4], v1[4];
                ldsm4(v0, s2u(&Vt[cur][ldrow     ][kv * 8 + ldcol]));
                ldsm4(v1, s2u(&Vt[cur][16 + ldrow][kv * 8 + ldcol]));
#pragma unroll
                for (int mi = 0; mi < 2; mi++) {
                    uint32_t pa[4];
                    pa[0] = __float_as_uint(s[mi][nt][0]);
                    pa[1] = __float_as_uint(s[mi][nt][2]);
                    pa[2] = __float_as_uint(s[mi][nt][1]);
                    pa[3] = __float_as_uint(s[mi][nt][3]);
                    mma_tf32(o[mi][0], pa, &v0[0]);
                    mma_tf32(o[mi][1], pa, &v0[2]);
                    mma_tf32(o[mi][2], pa, &v1[0]);
                    mma_tf32(o[mi][3], pa, &v1[2]);
                    mma_tf32(o5[mi], pa, bones);
                }
            }
        }
    }

#pragma unroll
    for (int mi = 0; mi < 2; mi++) {
        const float l0 = __shfl_sync(0xffffffffu, o5[mi][0], lane & ~3);
        const float l1 = __shfl_sync(0xffffffffu, o5[mi][2], lane & ~3);
        const float inv0 = 1.f / l0;
        const float inv1 = 1.f / l1;
        const int row0 = rbase + mi * 16 + g;
        const int base0 = (b * NTOK + row0) * DIM + h * HD;
        const int base1 = (b * NTOK + row0 + 8) * DIM + h * HD;
#pragma unroll
        for (int nn = 0; nn < 4; nn++) {
            *(float2*)&g_mid[base0 + nn * 8 + 2 * q] = make_float2(
                __uint_as_float(f2tf(o[mi][nn][0] * inv0)),
                __uint_as_float(f2tf(o[mi][nn][1] * inv0)));
            *(float2*)&g_mid[base1 + nn * 8 + 2 * q] = make_float2(
                __uint_as_float(f2tf(o[mi][nn][2] * inv1)),
                __uint_as_float(f2tf(o[mi][nn][3] * inv1)));
        }
    }
}

// ---------------- launch ----------------
extern "C" void kernel_launch(void* const* d_in, const int* in_sizes, int n_in,
                              void* d_out, int out_size)
{
    const float* x          = (const float*)d_in[0];
    const float* w_qkv      = (const float*)d_in[1];
    const float* b_qkv      = (const float*)d_in[2];
    const float* conv_w     = (const float*)d_in[3];
    const float* conv_b     = (const float*)d_in[4];
    const float* w_proj     = (const float*)d_in[5];
    const float* b_proj     = (const float*)d_in[6];
    const float* bias_table = (const float*)d_in[7];
    float* out = (float*)d_out;

    void *pxt = nullptr, *pwq = nullptr, *pwp = nullptr, *pmid = nullptr;
    cudaGetSymbolAddress(&pxt,  g_xt);
    cudaGetSymbolAddress(&pwq,  g_wqkv);
    cudaGetSymbolAddress(&pwp,  g_wproj);
    cudaGetSymbolAddress(&pmid, g_mid);

    // 0) one-time tf32 conversion of x, w_qkv, w_proj
    cvt_pack<<<3648, 256>>>(x, w_qkv, w_proj);

    // 1) fused QKV GEMM (wide 128x128 tiles), scatter into [b,h,n,d]
    gemm_wide<3 * DIM, 0><<<dim3(9, 64), 256>>>(
        (const uint32_t*)pxt, (const uint32_t*)pwq, b_qkv, nullptr);

    // 2) depthwise 3x3 conv; K normal layout, V transposed+permuted (coalesced)
    dwconv_kernel<<<(BATCH * NH * NTOK * 8) / 256, 256>>>(conv_w, conv_b);

    // 3) tensor-core flash attention (base-2 softmax) -> g_mid (tf32 bits)
    attn_mma_kernel<<<dim3(BATCH * NH, 8), 128>>>(bias_table);

    // 4) output projection (wide 128x128 tiles)
    gemm_wide<DIM, 1><<<dim3(3, 64), 256>>>(
        (const uint32_t*)pmid, (const uint32_t*)pwp, b_proj, out);
}